// round 14
// baseline (speedup 1.0000x reference)
#include <cuda_runtime.h>
#include <cuda_fp16.h>
#include <math.h>
#include <stdint.h>

// NT-Xent loss, B=4096, D=256, T=0.5 — int8 IMMA (m16n8k32) symmetric-half GEMM.
// Round 14: persistent CTAs + CTA-pair desync. The two CTAs resident on one SM
// start in lockstep (identical tile shapes), so their MUFU-heavy epilogues and
// tensor-heavy mainloops collide pipe-wise. A half-tile (~6000 cyc) skew on the
// second CTA per SM lets epilogue(A) overlap mainloop(B) every tile.

#define D      256
#define MAXB   4096
#define MAXN   (2 * MAXB)
#define INV_T  2.0f
#define QS     127.0f
#define QS2    16129.0f          // 127^2
#define NT     64                // tile grid dimension (8192/128)
#define LOG2E  1.4426950408889634f

__device__ int8_t   g_reps[MAXN * D];   // quantized normalized [z1; z2], 2 MB
__device__ float    g_pos[MAXN];
__device__ float    g_diag[MAXN];       // exp(INV_T*qnorm_i) — exact GEMM diagonal
__device__ float    g_rowsum[MAXN];
__device__ unsigned g_sm_turn[256];     // per-SM arrival tickets (zeroed per call)

// ---------------------------------------------------------------------------
// Kernel 1: normalize rows, quantize to int8, pos (fp32 exact), quantized diag.
// Also zeroes out[0] and the per-SM ticket array.
// ---------------------------------------------------------------------------
__global__ void normalize_kernel(const float* __restrict__ z1,
                                 const float* __restrict__ z2, int B,
                                 float* __restrict__ out) {
    if (blockIdx.x == 0) {
        if (threadIdx.x == 0) out[0] = 0.f;
        if (threadIdx.x < 256) g_sm_turn[threadIdx.x] = 0u;
    }

    int warp = (blockIdx.x * blockDim.x + threadIdx.x) >> 5;
    int lane = threadIdx.x & 31;
    if (warp >= B) return;

    const float4* a4 = (const float4*)(z1 + (size_t)warp * D);
    const float4* b4 = (const float4*)(z2 + (size_t)warp * D);

    float4 av[2], bv[2];
    float n1 = 0.f, n2 = 0.f, dp = 0.f;
#pragma unroll
    for (int t = 0; t < 2; t++) {
        float4 x = a4[lane + 32 * t];
        float4 y = b4[lane + 32 * t];
        av[t] = x; bv[t] = y;
        n1 += x.x * x.x + x.y * x.y + x.z * x.z + x.w * x.w;
        n2 += y.x * y.x + y.y * y.y + y.z * y.z + y.w * y.w;
        dp += x.x * y.x + x.y * y.y + x.z * y.z + x.w * y.w;
    }
#pragma unroll
    for (int off = 16; off; off >>= 1) {
        n1 += __shfl_xor_sync(0xffffffffu, n1, off);
        n2 += __shfl_xor_sync(0xffffffffu, n2, off);
        dp += __shfl_xor_sync(0xffffffffu, dp, off);
    }

    float inv1 = 1.f / fmaxf(sqrtf(n1), 1e-12f);
    float inv2 = 1.f / fmaxf(sqrtf(n2), 1e-12f);

    uint32_t* r1 = (uint32_t*)(g_reps + (size_t)warp * D);
    uint32_t* r2 = (uint32_t*)(g_reps + (size_t)(warp + B) * D);

    float qn1 = 0.f, qn2 = 0.f;
#pragma unroll
    for (int t = 0; t < 2; t++) {
        float xs[4] = { av[t].x * inv1, av[t].y * inv1, av[t].z * inv1, av[t].w * inv1 };
        float ys[4] = { bv[t].x * inv2, bv[t].y * inv2, bv[t].z * inv2, bv[t].w * inv2 };
        uint32_t pa = 0, pb = 0;
#pragma unroll
        for (int e = 0; e < 4; e++) {
            int qa = __float2int_rn(QS * xs[e]);
            int qb = __float2int_rn(QS * ys[e]);
            qn1 += (float)(qa * qa);
            qn2 += (float)(qb * qb);
            pa |= ((uint32_t)(uint8_t)(int8_t)qa) << (8 * e);
            pb |= ((uint32_t)(uint8_t)(int8_t)qb) << (8 * e);
        }
        r1[lane + 32 * t] = pa;
        r2[lane + 32 * t] = pb;
    }
#pragma unroll
    for (int off = 16; off; off >>= 1) {
        qn1 += __shfl_xor_sync(0xffffffffu, qn1, off);
        qn2 += __shfl_xor_sync(0xffffffffu, qn2, off);
    }

    if (lane == 0) {
        float pos = dp * inv1 * inv2 * INV_T;
        g_pos[warp]        = pos;
        g_pos[warp + B]    = pos;
        g_diag[warp]       = __expf(INV_T * qn1 / QS2);
        g_diag[warp + B]   = __expf(INV_T * qn2 / QS2);
        g_rowsum[warp]     = 0.f;
        g_rowsum[warp + B] = 0.f;
    }
}

// ---------------------------------------------------------------------------
// PTX helpers
// ---------------------------------------------------------------------------
__device__ __forceinline__ uint32_t smem_u32(const void* p) {
    return (uint32_t)__cvta_generic_to_shared(p);
}
__device__ __forceinline__ void cpasync16(uint32_t dst, const void* src) {
    asm volatile("cp.async.cg.shared.global [%0], [%1], 16;"
                 :: "r"(dst), "l"(src) : "memory");
}
#define CP_COMMIT() asm volatile("cp.async.commit_group;" ::: "memory")
#define CP_WAIT0()  asm volatile("cp.async.wait_group 0;" ::: "memory")

__device__ __forceinline__ void ldsm_x4(uint32_t* r, uint32_t addr) {
    asm volatile("ldmatrix.sync.aligned.m8n8.x4.shared.b16 {%0,%1,%2,%3}, [%4];"
                 : "=r"(r[0]), "=r"(r[1]), "=r"(r[2]), "=r"(r[3]) : "r"(addr));
}
__device__ __forceinline__ void mma16832s8(int* c, const uint32_t* a,
                                           const uint32_t* b) {
    asm volatile(
        "mma.sync.aligned.m16n8k32.row.col.s32.s8.s8.s32 "
        "{%0,%1,%2,%3}, {%4,%5,%6,%7}, {%8,%9}, {%0,%1,%2,%3};"
        : "+r"(c[0]), "+r"(c[1]), "+r"(c[2]), "+r"(c[3])
        : "r"(a[0]), "r"(a[1]), "r"(a[2]), "r"(a[3]), "r"(b[0]), "r"(b[1]));
}

// upper-triangle tile index -> (bi, bj)
__device__ __forceinline__ void decode_tile(int t, int& bi, int& bj) {
    float f = 2.0f * NT + 1.0f;
    int b = (int)((f - sqrtf(f * f - 8.0f * (float)t)) * 0.5f);
    if (b > NT - 1) b = NT - 1;
    while (b * NT - b * (b - 1) / 2 > t) b--;
    while ((b + 1) * NT - (b + 1) * b / 2 <= t) b++;
    bi = b;
    bj = b + (t - (b * NT - b * (b - 1) / 2));
}

// ---------------------------------------------------------------------------
// Kernel 2: persistent symmetric-half fused IMMA GEMM + exp row/col-sum.
// 296 CTAs grid-stride over 2080 tiles; cross-tile chunk-0 prefetch; second
// CTA on each SM skews by ~6000 cyc to overlap epilogue with peer mainloop.
// ---------------------------------------------------------------------------
#define BM 128
#define BN 128
#define BK 64             // int8 elements (bytes) per k-chunk
#define NKT (D / BK)      // 4
#define RSB 80            // padded row stride in bytes
#define NTILES (NT * (NT + 1) / 2)   // 2080
#define GRID_P 296                   // 2 CTAs x 148 SMs
#define SKEW_CYC 6000

__global__ __launch_bounds__(128, 2) void simsum_kernel() {
    __shared__ __align__(16) int8_t As[2][BM * RSB];
    __shared__ __align__(16) int8_t Bs[2][BN * RSB];
    __shared__ float rowbuf[BM];
    __shared__ float colbuf[BN];
    __shared__ unsigned s_turn;

    int tid  = threadIdx.x;
    int wid  = tid >> 5;
    int lane = tid & 31;

    int wm = wid >> 1;           // 0..1
    int wn = wid & 1;            // 0..1
    int mbase = wm * 64;
    int nbase = wn * 64;

    int crow0 = tid >> 2;        // 0..31
    int cseg  = tid & 3;         // 16B segment within 64B row-chunk

    uint32_t as_addr[2] = { smem_u32(As[0]), smem_u32(As[1]) };
    uint32_t bs_addr[2] = { smem_u32(Bs[0]), smem_u32(Bs[1]) };

    // ldmatrix per-lane address components (byte units)
    int a_rowoff = mbase + (lane & 7) + ((lane >> 3) & 1) * 8;   // + mi*16
    int a_byte   = (lane >> 4) * 16;                             // + kk*32
    int b_rowoff = nbase + (lane & 7) + ((lane >> 4) & 1) * 8;   // + nh*16
    int b_byte   = ((lane >> 3) & 1) * 16;                       // + kk*32

    int g  = lane >> 2;       // accumulator row-group (0..7)
    int tc = lane & 3;        // accumulator col-pair (0..3)
    const float SC2 = (INV_T / QS2) * LOG2E;   // exp(x) = exp2(x*log2e)

    auto issue_copy = [&](int s, const int8_t* Ag, const int8_t* Bg, int kt) {
        int k0 = kt * BK;
#pragma unroll
        for (int i = 0; i < 4; i++) {
            int row = crow0 + 32 * i;
            uint32_t dsto = (uint32_t)(row * RSB + cseg * 16);
            cpasync16(as_addr[s] + dsto, Ag + (size_t)row * D + k0 + cseg * 16);
            cpasync16(bs_addr[s] + dsto, Bg + (size_t)row * D + k0 + cseg * 16);
        }
        CP_COMMIT();
    };

    int t0 = blockIdx.x;
    if (t0 >= NTILES) return;

    int bi, bj;
    decode_tile(t0, bi, bj);
    const int8_t* Ag = g_reps + (size_t)bi * BM * D;
    const int8_t* Bg = g_reps + (size_t)bj * BN * D;

    // prologue: first tile's chunk 0 (in flight during any skew spin)
    issue_copy(0, Ag, Bg, 0);

    // ---- CTA-pair desync: second CTA to arrive on this SM skews ~SKEW_CYC --
    if (tid == 0) {
        unsigned smid;
        asm volatile("mov.u32 %0, %%smid;" : "=r"(smid));
        s_turn = atomicAdd(&g_sm_turn[smid & 255u], 1u);
    }
    __syncthreads();
    if (s_turn & 1u) {
        long long start = clock64();
        while (clock64() - start < SKEW_CYC) {}
    }

    for (int t = t0; t < NTILES; t += GRID_P) {
        bool offdiag = (bi != bj);
        int bin = 0, bjn = 0;
        const int8_t* Agn = 0;
        const int8_t* Bgn = 0;
        bool have_next = (t + GRID_P < NTILES);
        if (have_next) {
            decode_tile(t + GRID_P, bin, bjn);
            Agn = g_reps + (size_t)bin * BM * D;
            Bgn = g_reps + (size_t)bjn * BN * D;
        }

        int acc[4][8][4];
#pragma unroll
        for (int i = 0; i < 4; i++)
#pragma unroll
            for (int j = 0; j < 8; j++)
#pragma unroll
                for (int k = 0; k < 4; k++) acc[i][j][k] = 0;

#pragma unroll
        for (int kt = 0; kt < NKT; kt++) {
            CP_WAIT0();          // chunk kt retired
            __syncthreads();     // data visible; other stage drained
            if (kt == 0) {
                if (tid < BM) { rowbuf[tid] = 0.f; colbuf[tid] = 0.f; }
            }
            if (kt + 1 < NKT) {
                issue_copy((kt + 1) & 1, Ag, Bg, kt + 1);
            } else if (have_next) {
                issue_copy(0, Agn, Bgn, 0);   // next tile chunk0 -> stage 0
            }

            int s = kt & 1;
            uint32_t ab = as_addr[s];
            uint32_t bb = bs_addr[s];

#pragma unroll
            for (int kk = 0; kk < 2; kk++) {
                uint32_t a[4][4], b[4][4];
#pragma unroll
                for (int mi = 0; mi < 4; mi++) {
                    uint32_t addr = ab + (uint32_t)((a_rowoff + mi * 16) * RSB
                                                    + kk * 32 + a_byte);
                    ldsm_x4(a[mi], addr);
                }
#pragma unroll
                for (int nh = 0; nh < 4; nh++) {
                    uint32_t addr = bb + (uint32_t)((b_rowoff + nh * 16) * RSB
                                                    + kk * 32 + b_byte);
                    ldsm_x4(b[nh], addr);
                }
#pragma unroll
                for (int mi = 0; mi < 4; mi++)
#pragma unroll
                    for (int nh = 0; nh < 4; nh++) {
                        mma16832s8(acc[mi][2 * nh],     a[mi], &b[nh][0]);
                        mma16832s8(acc[mi][2 * nh + 1], a[mi], &b[nh][2]);
                    }
            }
        }

        // ---- epilogue ----
        float cs[8][2];
#pragma unroll
        for (int ni = 0; ni < 8; ni++) { cs[ni][0] = 0.f; cs[ni][1] = 0.f; }

#pragma unroll
        for (int mi = 0; mi < 4; mi++) {
#pragma unroll
            for (int h = 0; h < 2; h++) {
                float s = 0.f;
#pragma unroll
                for (int ni = 0; ni < 8; ni++) {
#pragma unroll
                    for (int e = 0; e < 2; e++) {
                        float ex = exp2f(SC2 * (float)acc[mi][ni][2 * h + e]);
                        s += ex;
                        cs[ni][e] += ex;
                    }
                }
                s += __shfl_xor_sync(0xffffffffu, s, 1);
                s += __shfl_xor_sync(0xffffffffu, s, 2);
                if (tc == 0)
                    atomicAdd(&rowbuf[mbase + mi * 16 + h * 8 + g], s);
            }
        }
        if (offdiag) {
#pragma unroll
            for (int ni = 0; ni < 8; ni++) {
#pragma unroll
                for (int e = 0; e < 2; e++) {
                    float c = cs[ni][e];
                    c += __shfl_xor_sync(0xffffffffu, c, 4);
                    c += __shfl_xor_sync(0xffffffffu, c, 8);
                    c += __shfl_xor_sync(0xffffffffu, c, 16);
                    if (g == 0)
                        atomicAdd(&colbuf[nbase + ni * 8 + 2 * tc + e], c);
                }
            }
        }
        __syncthreads();   // all smem atomics done before reading buffers

        if (tid < BM) {
            atomicAdd(&g_rowsum[bi * BM + tid], rowbuf[tid]);
            if (offdiag)
                atomicAdd(&g_rowsum[bj * BN + tid], colbuf[tid]);
        }

        bi = bin; bj = bjn; Ag = Agn; Bg = Bgn;
    }
}

// ---------------------------------------------------------------------------
// Kernel 3: finalize (parallel).
// ---------------------------------------------------------------------------
__global__ void finalize_kernel(float* __restrict__ out, int N2) {
    __shared__ float sdata[256];
    int tid  = threadIdx.x;
    int gidx = blockIdx.x * 256 + tid;
    int stride = gridDim.x * 256;

    float local = 0.f;
    for (int i = gidx; i < N2; i += stride) {
        float pos = g_pos[i];
        float rs  = g_rowsum[i] + __expf(pos) - g_diag[i];
        local += logf(rs) - pos;
    }
    sdata[tid] = local;
    __syncthreads();
#pragma unroll
    for (int s = 128; s; s >>= 1) {
        if (tid < s) sdata[tid] += sdata[tid + s];
        __syncthreads();
    }
    if (tid == 0) atomicAdd(out, sdata[0] / (float)N2);
}

// ---------------------------------------------------------------------------
extern "C" void kernel_launch(void* const* d_in, const int* in_sizes, int n_in,
                              void* d_out, int out_size) {
    const float* z1 = (const float*)d_in[0];
    const float* z2 = (const float*)d_in[1];
    int B  = in_sizes[0] / D;   // 4096
    int N2 = 2 * B;             // 8192

    int threads = 256;
    int blocks  = (B * 32 + threads - 1) / threads;
    normalize_kernel<<<blocks, threads>>>(z1, z2, B, (float*)d_out);

    simsum_kernel<<<GRID_P, 128>>>();

    finalize_kernel<<<16, 256>>>((float*)d_out, N2);
}

// round 15
// speedup vs baseline: 1.1922x; 1.1922x over previous
#include <cuda_runtime.h>
#include <cuda_fp16.h>
#include <math.h>
#include <stdint.h>

// NT-Xent loss, B=4096, D=256, T=0.5 — int8 IMMA (m16n8k32) symmetric-half GEMM.
// Round 15: R13 design (persistent CTAs + cross-tile prefetch, NO desync) with
// a slimmed epilogue: warp-reduced partials go straight to global atomics,
// removing the smem staging buffers, their zeroing, and one barrier per tile.

#define D      256
#define MAXB   4096
#define MAXN   (2 * MAXB)
#define INV_T  2.0f
#define QS     127.0f
#define QS2    16129.0f          // 127^2
#define NT     64                // tile grid dimension (8192/128)
#define LOG2E  1.4426950408889634f

__device__ int8_t g_reps[MAXN * D];   // quantized normalized [z1; z2], 2 MB
__device__ float  g_pos[MAXN];
__device__ float  g_diag[MAXN];       // exp(INV_T*qnorm_i) — exact GEMM diagonal
__device__ float  g_rowsum[MAXN];

// ---------------------------------------------------------------------------
// Kernel 1: normalize rows, quantize to int8, pos (fp32 exact), quantized diag.
// Also zeroes out[0] for the parallel finalize.
// ---------------------------------------------------------------------------
__global__ void normalize_kernel(const float* __restrict__ z1,
                                 const float* __restrict__ z2, int B,
                                 float* __restrict__ out) {
    if (blockIdx.x == 0 && threadIdx.x == 0) out[0] = 0.f;

    int warp = (blockIdx.x * blockDim.x + threadIdx.x) >> 5;
    int lane = threadIdx.x & 31;
    if (warp >= B) return;

    const float4* a4 = (const float4*)(z1 + (size_t)warp * D);
    const float4* b4 = (const float4*)(z2 + (size_t)warp * D);

    float4 av[2], bv[2];
    float n1 = 0.f, n2 = 0.f, dp = 0.f;
#pragma unroll
    for (int t = 0; t < 2; t++) {
        float4 x = a4[lane + 32 * t];
        float4 y = b4[lane + 32 * t];
        av[t] = x; bv[t] = y;
        n1 += x.x * x.x + x.y * x.y + x.z * x.z + x.w * x.w;
        n2 += y.x * y.x + y.y * y.y + y.z * y.z + y.w * y.w;
        dp += x.x * y.x + x.y * y.y + x.z * y.z + x.w * y.w;
    }
#pragma unroll
    for (int off = 16; off; off >>= 1) {
        n1 += __shfl_xor_sync(0xffffffffu, n1, off);
        n2 += __shfl_xor_sync(0xffffffffu, n2, off);
        dp += __shfl_xor_sync(0xffffffffu, dp, off);
    }

    float inv1 = 1.f / fmaxf(sqrtf(n1), 1e-12f);
    float inv2 = 1.f / fmaxf(sqrtf(n2), 1e-12f);

    uint32_t* r1 = (uint32_t*)(g_reps + (size_t)warp * D);
    uint32_t* r2 = (uint32_t*)(g_reps + (size_t)(warp + B) * D);

    float qn1 = 0.f, qn2 = 0.f;
#pragma unroll
    for (int t = 0; t < 2; t++) {
        float xs[4] = { av[t].x * inv1, av[t].y * inv1, av[t].z * inv1, av[t].w * inv1 };
        float ys[4] = { bv[t].x * inv2, bv[t].y * inv2, bv[t].z * inv2, bv[t].w * inv2 };
        uint32_t pa = 0, pb = 0;
#pragma unroll
        for (int e = 0; e < 4; e++) {
            int qa = __float2int_rn(QS * xs[e]);
            int qb = __float2int_rn(QS * ys[e]);
            qn1 += (float)(qa * qa);
            qn2 += (float)(qb * qb);
            pa |= ((uint32_t)(uint8_t)(int8_t)qa) << (8 * e);
            pb |= ((uint32_t)(uint8_t)(int8_t)qb) << (8 * e);
        }
        r1[lane + 32 * t] = pa;
        r2[lane + 32 * t] = pb;
    }
#pragma unroll
    for (int off = 16; off; off >>= 1) {
        qn1 += __shfl_xor_sync(0xffffffffu, qn1, off);
        qn2 += __shfl_xor_sync(0xffffffffu, qn2, off);
    }

    if (lane == 0) {
        float pos = dp * inv1 * inv2 * INV_T;
        g_pos[warp]        = pos;
        g_pos[warp + B]    = pos;
        g_diag[warp]       = __expf(INV_T * qn1 / QS2);
        g_diag[warp + B]   = __expf(INV_T * qn2 / QS2);
        g_rowsum[warp]     = 0.f;
        g_rowsum[warp + B] = 0.f;
    }
}

// ---------------------------------------------------------------------------
// PTX helpers
// ---------------------------------------------------------------------------
__device__ __forceinline__ uint32_t smem_u32(const void* p) {
    return (uint32_t)__cvta_generic_to_shared(p);
}
__device__ __forceinline__ void cpasync16(uint32_t dst, const void* src) {
    asm volatile("cp.async.cg.shared.global [%0], [%1], 16;"
                 :: "r"(dst), "l"(src) : "memory");
}
#define CP_COMMIT() asm volatile("cp.async.commit_group;" ::: "memory")
#define CP_WAIT0()  asm volatile("cp.async.wait_group 0;" ::: "memory")

__device__ __forceinline__ void ldsm_x4(uint32_t* r, uint32_t addr) {
    asm volatile("ldmatrix.sync.aligned.m8n8.x4.shared.b16 {%0,%1,%2,%3}, [%4];"
                 : "=r"(r[0]), "=r"(r[1]), "=r"(r[2]), "=r"(r[3]) : "r"(addr));
}
__device__ __forceinline__ void mma16832s8(int* c, const uint32_t* a,
                                           const uint32_t* b) {
    asm volatile(
        "mma.sync.aligned.m16n8k32.row.col.s32.s8.s8.s32 "
        "{%0,%1,%2,%3}, {%4,%5,%6,%7}, {%8,%9}, {%0,%1,%2,%3};"
        : "+r"(c[0]), "+r"(c[1]), "+r"(c[2]), "+r"(c[3])
        : "r"(a[0]), "r"(a[1]), "r"(a[2]), "r"(a[3]), "r"(b[0]), "r"(b[1]));
}

// upper-triangle tile index -> (bi, bj)
__device__ __forceinline__ void decode_tile(int t, int& bi, int& bj) {
    float f = 2.0f * NT + 1.0f;
    int b = (int)((f - sqrtf(f * f - 8.0f * (float)t)) * 0.5f);
    if (b > NT - 1) b = NT - 1;
    while (b * NT - b * (b - 1) / 2 > t) b--;
    while ((b + 1) * NT - (b + 1) * b / 2 <= t) b++;
    bi = b;
    bj = b + (t - (b * NT - b * (b - 1) / 2));
}

// ---------------------------------------------------------------------------
// Kernel 2: persistent symmetric-half fused IMMA GEMM + exp row/col-sum.
// 296 CTAs grid-stride over 2080 tiles; cross-tile chunk-0 prefetch; epilogue
// atomics go straight to g_rowsum (no smem staging).
// ---------------------------------------------------------------------------
#define BM 128
#define BN 128
#define BK 64             // int8 elements (bytes) per k-chunk
#define NKT (D / BK)      // 4
#define RSB 80            // padded row stride in bytes
#define NTILES (NT * (NT + 1) / 2)   // 2080
#define GRID_P 296                   // 2 CTAs x 148 SMs

__global__ __launch_bounds__(128, 2) void simsum_kernel() {
    __shared__ __align__(16) int8_t As[2][BM * RSB];
    __shared__ __align__(16) int8_t Bs[2][BN * RSB];

    int tid  = threadIdx.x;
    int wid  = tid >> 5;
    int lane = tid & 31;

    int wm = wid >> 1;           // 0..1
    int wn = wid & 1;            // 0..1
    int mbase = wm * 64;
    int nbase = wn * 64;

    int crow0 = tid >> 2;        // 0..31
    int cseg  = tid & 3;         // 16B segment within 64B row-chunk

    uint32_t as_addr[2] = { smem_u32(As[0]), smem_u32(As[1]) };
    uint32_t bs_addr[2] = { smem_u32(Bs[0]), smem_u32(Bs[1]) };

    // ldmatrix per-lane address components (byte units)
    int a_rowoff = mbase + (lane & 7) + ((lane >> 3) & 1) * 8;   // + mi*16
    int a_byte   = (lane >> 4) * 16;                             // + kk*32
    int b_rowoff = nbase + (lane & 7) + ((lane >> 4) & 1) * 8;   // + nh*16
    int b_byte   = ((lane >> 3) & 1) * 16;                       // + kk*32

    int g  = lane >> 2;       // accumulator row-group (0..7)
    int tc = lane & 3;        // accumulator col-pair (0..3)
    const float SC2 = (INV_T / QS2) * LOG2E;   // exp(x) = exp2(x*log2e)

    auto issue_copy = [&](int s, const int8_t* Ag, const int8_t* Bg, int kt) {
        int k0 = kt * BK;
#pragma unroll
        for (int i = 0; i < 4; i++) {
            int row = crow0 + 32 * i;
            uint32_t dsto = (uint32_t)(row * RSB + cseg * 16);
            cpasync16(as_addr[s] + dsto, Ag + (size_t)row * D + k0 + cseg * 16);
            cpasync16(bs_addr[s] + dsto, Bg + (size_t)row * D + k0 + cseg * 16);
        }
        CP_COMMIT();
    };

    int t0 = blockIdx.x;
    if (t0 >= NTILES) return;

    int bi, bj;
    decode_tile(t0, bi, bj);
    const int8_t* Ag = g_reps + (size_t)bi * BM * D;
    const int8_t* Bg = g_reps + (size_t)bj * BN * D;

    // prologue: first tile's chunk 0
    issue_copy(0, Ag, Bg, 0);

    for (int t = t0; t < NTILES; t += GRID_P) {
        bool offdiag = (bi != bj);
        int bin = 0, bjn = 0;
        const int8_t* Agn = 0;
        const int8_t* Bgn = 0;
        bool have_next = (t + GRID_P < NTILES);
        if (have_next) {
            decode_tile(t + GRID_P, bin, bjn);
            Agn = g_reps + (size_t)bin * BM * D;
            Bgn = g_reps + (size_t)bjn * BN * D;
        }

        int acc[4][8][4];
#pragma unroll
        for (int i = 0; i < 4; i++)
#pragma unroll
            for (int j = 0; j < 8; j++)
#pragma unroll
                for (int k = 0; k < 4; k++) acc[i][j][k] = 0;

#pragma unroll
        for (int kt = 0; kt < NKT; kt++) {
            CP_WAIT0();          // chunk kt retired
            __syncthreads();     // data visible; other stage drained
            if (kt + 1 < NKT) {
                issue_copy((kt + 1) & 1, Ag, Bg, kt + 1);
            } else if (have_next) {
                issue_copy(0, Agn, Bgn, 0);   // next tile chunk0 -> stage 0
            }

            int s = kt & 1;
            uint32_t ab = as_addr[s];
            uint32_t bb = bs_addr[s];

#pragma unroll
            for (int kk = 0; kk < 2; kk++) {
                uint32_t a[4][4], b[4][4];
#pragma unroll
                for (int mi = 0; mi < 4; mi++) {
                    uint32_t addr = ab + (uint32_t)((a_rowoff + mi * 16) * RSB
                                                    + kk * 32 + a_byte);
                    ldsm_x4(a[mi], addr);
                }
#pragma unroll
                for (int nh = 0; nh < 4; nh++) {
                    uint32_t addr = bb + (uint32_t)((b_rowoff + nh * 16) * RSB
                                                    + kk * 32 + b_byte);
                    ldsm_x4(b[nh], addr);
                }
#pragma unroll
                for (int mi = 0; mi < 4; mi++)
#pragma unroll
                    for (int nh = 0; nh < 4; nh++) {
                        mma16832s8(acc[mi][2 * nh],     a[mi], &b[nh][0]);
                        mma16832s8(acc[mi][2 * nh + 1], a[mi], &b[nh][2]);
                    }
            }
        }

        // ---- epilogue: exp + warp reduce -> DIRECT global atomics ----
        float* growA = g_rowsum + bi * BM;
        float* growB = g_rowsum + bj * BN;

        float cs[8][2];
#pragma unroll
        for (int ni = 0; ni < 8; ni++) { cs[ni][0] = 0.f; cs[ni][1] = 0.f; }

#pragma unroll
        for (int mi = 0; mi < 4; mi++) {
#pragma unroll
            for (int h = 0; h < 2; h++) {
                float s = 0.f;
#pragma unroll
                for (int ni = 0; ni < 8; ni++) {
#pragma unroll
                    for (int e = 0; e < 2; e++) {
                        float ex = exp2f(SC2 * (float)acc[mi][ni][2 * h + e]);
                        s += ex;
                        cs[ni][e] += ex;
                    }
                }
                s += __shfl_xor_sync(0xffffffffu, s, 1);
                s += __shfl_xor_sync(0xffffffffu, s, 2);
                if (tc == 0)
                    atomicAdd(&growA[mbase + mi * 16 + h * 8 + g], s);
            }
        }
        if (offdiag) {
#pragma unroll
            for (int ni = 0; ni < 8; ni++) {
#pragma unroll
                for (int e = 0; e < 2; e++) {
                    float c = cs[ni][e];
                    c += __shfl_xor_sync(0xffffffffu, c, 4);
                    c += __shfl_xor_sync(0xffffffffu, c, 8);
                    c += __shfl_xor_sync(0xffffffffu, c, 16);
                    if (g == 0)
                        atomicAdd(&growB[nbase + ni * 8 + 2 * tc + e], c);
                }
            }
        }
        // No trailing barrier needed: the next tile's kt=0 CP_WAIT0+sync
        // orders smem stage reuse; global atomics need no ordering.

        bi = bin; bj = bjn; Ag = Agn; Bg = Bgn;
    }
}

// ---------------------------------------------------------------------------
// Kernel 3: finalize (parallel).
// ---------------------------------------------------------------------------
__global__ void finalize_kernel(float* __restrict__ out, int N2) {
    __shared__ float sdata[256];
    int tid  = threadIdx.x;
    int gidx = blockIdx.x * 256 + tid;
    int stride = gridDim.x * 256;

    float local = 0.f;
    for (int i = gidx; i < N2; i += stride) {
        float pos = g_pos[i];
        float rs  = g_rowsum[i] + __expf(pos) - g_diag[i];
        local += logf(rs) - pos;
    }
    sdata[tid] = local;
    __syncthreads();
#pragma unroll
    for (int s = 128; s; s >>= 1) {
        if (tid < s) sdata[tid] += sdata[tid + s];
        __syncthreads();
    }
    if (tid == 0) atomicAdd(out, sdata[0] / (float)N2);
}

// ---------------------------------------------------------------------------
extern "C" void kernel_launch(void* const* d_in, const int* in_sizes, int n_in,
                              void* d_out, int out_size) {
    const float* z1 = (const float*)d_in[0];
    const float* z2 = (const float*)d_in[1];
    int B  = in_sizes[0] / D;   // 4096
    int N2 = 2 * B;             // 8192

    int threads = 256;
    int blocks  = (B * 32 + threads - 1) / threads;
    normalize_kernel<<<blocks, threads>>>(z1, z2, B, (float*)d_out);

    simsum_kernel<<<GRID_P, 128>>>();

    finalize_kernel<<<16, 256>>>((float*)d_out, N2);
}

// round 16
// speedup vs baseline: 1.2643x; 1.0605x over previous
#include <cuda_runtime.h>
#include <cuda_fp16.h>
#include <math.h>
#include <stdint.h>

// NT-Xent loss, B=4096, D=256, T=0.5 — int8 IMMA (m16n8k32) symmetric-half GEMM.
// Round 16: R15 + f16x2 epilogue — h2exp2 (ex2.approx.f16x2) does 2 exps per
// MUFU op and HADD2 halves the reduction adds. Direct-global atomics kept.

#define D      256
#define MAXB   4096
#define MAXN   (2 * MAXB)
#define INV_T  2.0f
#define QS     127.0f
#define QS2    16129.0f          // 127^2
#define NT     64                // tile grid dimension (8192/128)
#define LOG2E  1.4426950408889634f

__device__ int8_t g_reps[MAXN * D];   // quantized normalized [z1; z2], 2 MB
__device__ float  g_pos[MAXN];
__device__ float  g_diag[MAXN];       // exp(INV_T*qnorm_i) — exact GEMM diagonal
__device__ float  g_rowsum[MAXN];

// ---------------------------------------------------------------------------
// Kernel 1: normalize rows, quantize to int8, pos (fp32 exact), quantized diag.
// ---------------------------------------------------------------------------
__global__ void normalize_kernel(const float* __restrict__ z1,
                                 const float* __restrict__ z2, int B,
                                 float* __restrict__ out) {
    if (blockIdx.x == 0 && threadIdx.x == 0) out[0] = 0.f;

    int warp = (blockIdx.x * blockDim.x + threadIdx.x) >> 5;
    int lane = threadIdx.x & 31;
    if (warp >= B) return;

    const float4* a4 = (const float4*)(z1 + (size_t)warp * D);
    const float4* b4 = (const float4*)(z2 + (size_t)warp * D);

    float4 av[2], bv[2];
    float n1 = 0.f, n2 = 0.f, dp = 0.f;
#pragma unroll
    for (int t = 0; t < 2; t++) {
        float4 x = a4[lane + 32 * t];
        float4 y = b4[lane + 32 * t];
        av[t] = x; bv[t] = y;
        n1 += x.x * x.x + x.y * x.y + x.z * x.z + x.w * x.w;
        n2 += y.x * y.x + y.y * y.y + y.z * y.z + y.w * y.w;
        dp += x.x * y.x + x.y * y.y + x.z * y.z + x.w * y.w;
    }
#pragma unroll
    for (int off = 16; off; off >>= 1) {
        n1 += __shfl_xor_sync(0xffffffffu, n1, off);
        n2 += __shfl_xor_sync(0xffffffffu, n2, off);
        dp += __shfl_xor_sync(0xffffffffu, dp, off);
    }

    float inv1 = 1.f / fmaxf(sqrtf(n1), 1e-12f);
    float inv2 = 1.f / fmaxf(sqrtf(n2), 1e-12f);

    uint32_t* r1 = (uint32_t*)(g_reps + (size_t)warp * D);
    uint32_t* r2 = (uint32_t*)(g_reps + (size_t)(warp + B) * D);

    float qn1 = 0.f, qn2 = 0.f;
#pragma unroll
    for (int t = 0; t < 2; t++) {
        float xs[4] = { av[t].x * inv1, av[t].y * inv1, av[t].z * inv1, av[t].w * inv1 };
        float ys[4] = { bv[t].x * inv2, bv[t].y * inv2, bv[t].z * inv2, bv[t].w * inv2 };
        uint32_t pa = 0, pb = 0;
#pragma unroll
        for (int e = 0; e < 4; e++) {
            int qa = __float2int_rn(QS * xs[e]);
            int qb = __float2int_rn(QS * ys[e]);
            qn1 += (float)(qa * qa);
            qn2 += (float)(qb * qb);
            pa |= ((uint32_t)(uint8_t)(int8_t)qa) << (8 * e);
            pb |= ((uint32_t)(uint8_t)(int8_t)qb) << (8 * e);
        }
        r1[lane + 32 * t] = pa;
        r2[lane + 32 * t] = pb;
    }
#pragma unroll
    for (int off = 16; off; off >>= 1) {
        qn1 += __shfl_xor_sync(0xffffffffu, qn1, off);
        qn2 += __shfl_xor_sync(0xffffffffu, qn2, off);
    }

    if (lane == 0) {
        float pos = dp * inv1 * inv2 * INV_T;
        g_pos[warp]        = pos;
        g_pos[warp + B]    = pos;
        g_diag[warp]       = __expf(INV_T * qn1 / QS2);
        g_diag[warp + B]   = __expf(INV_T * qn2 / QS2);
        g_rowsum[warp]     = 0.f;
        g_rowsum[warp + B] = 0.f;
    }
}

// ---------------------------------------------------------------------------
// PTX helpers
// ---------------------------------------------------------------------------
__device__ __forceinline__ uint32_t smem_u32(const void* p) {
    return (uint32_t)__cvta_generic_to_shared(p);
}
__device__ __forceinline__ void cpasync16(uint32_t dst, const void* src) {
    asm volatile("cp.async.cg.shared.global [%0], [%1], 16;"
                 :: "r"(dst), "l"(src) : "memory");
}
#define CP_COMMIT() asm volatile("cp.async.commit_group;" ::: "memory")
#define CP_WAIT0()  asm volatile("cp.async.wait_group 0;" ::: "memory")

__device__ __forceinline__ void ldsm_x4(uint32_t* r, uint32_t addr) {
    asm volatile("ldmatrix.sync.aligned.m8n8.x4.shared.b16 {%0,%1,%2,%3}, [%4];"
                 : "=r"(r[0]), "=r"(r[1]), "=r"(r[2]), "=r"(r[3]) : "r"(addr));
}
__device__ __forceinline__ void mma16832s8(int* c, const uint32_t* a,
                                           const uint32_t* b) {
    asm volatile(
        "mma.sync.aligned.m16n8k32.row.col.s32.s8.s8.s32 "
        "{%0,%1,%2,%3}, {%4,%5,%6,%7}, {%8,%9}, {%0,%1,%2,%3};"
        : "+r"(c[0]), "+r"(c[1]), "+r"(c[2]), "+r"(c[3])
        : "r"(a[0]), "r"(a[1]), "r"(a[2]), "r"(a[3]), "r"(b[0]), "r"(b[1]));
}

// upper-triangle tile index -> (bi, bj)
__device__ __forceinline__ void decode_tile(int t, int& bi, int& bj) {
    float f = 2.0f * NT + 1.0f;
    int b = (int)((f - sqrtf(f * f - 8.0f * (float)t)) * 0.5f);
    if (b > NT - 1) b = NT - 1;
    while (b * NT - b * (b - 1) / 2 > t) b--;
    while ((b + 1) * NT - (b + 1) * b / 2 <= t) b++;
    bi = b;
    bj = b + (t - (b * NT - b * (b - 1) / 2));
}

__device__ __forceinline__ __half2 shfl_xor_h2(__half2 v, int off) {
    uint32_t u = *(uint32_t*)&v;
    u = __shfl_xor_sync(0xffffffffu, u, off);
    return *(__half2*)&u;
}

// ---------------------------------------------------------------------------
// Kernel 2: persistent symmetric-half fused IMMA GEMM + f16x2 exp epilogue.
// ---------------------------------------------------------------------------
#define BM 128
#define BN 128
#define BK 64             // int8 elements (bytes) per k-chunk
#define NKT (D / BK)      // 4
#define RSB 80            // padded row stride in bytes
#define NTILES (NT * (NT + 1) / 2)   // 2080
#define GRID_P 296                   // 2 CTAs x 148 SMs

__global__ __launch_bounds__(128, 2) void simsum_kernel() {
    __shared__ __align__(16) int8_t As[2][BM * RSB];
    __shared__ __align__(16) int8_t Bs[2][BN * RSB];

    int tid  = threadIdx.x;
    int wid  = tid >> 5;
    int lane = tid & 31;

    int wm = wid >> 1;           // 0..1
    int wn = wid & 1;            // 0..1
    int mbase = wm * 64;
    int nbase = wn * 64;

    int crow0 = tid >> 2;        // 0..31
    int cseg  = tid & 3;         // 16B segment within 64B row-chunk

    uint32_t as_addr[2] = { smem_u32(As[0]), smem_u32(As[1]) };
    uint32_t bs_addr[2] = { smem_u32(Bs[0]), smem_u32(Bs[1]) };

    // ldmatrix per-lane address components (byte units)
    int a_rowoff = mbase + (lane & 7) + ((lane >> 3) & 1) * 8;   // + mi*16
    int a_byte   = (lane >> 4) * 16;                             // + kk*32
    int b_rowoff = nbase + (lane & 7) + ((lane >> 4) & 1) * 8;   // + nh*16
    int b_byte   = ((lane >> 3) & 1) * 16;                       // + kk*32

    int g  = lane >> 2;       // accumulator row-group (0..7)
    int tc = lane & 3;        // accumulator col-pair (0..3)
    const float SC2 = (INV_T / QS2) * LOG2E;   // exp(x) = exp2(x*log2e)

    auto issue_copy = [&](int s, const int8_t* Ag, const int8_t* Bg, int kt) {
        int k0 = kt * BK;
#pragma unroll
        for (int i = 0; i < 4; i++) {
            int row = crow0 + 32 * i;
            uint32_t dsto = (uint32_t)(row * RSB + cseg * 16);
            cpasync16(as_addr[s] + dsto, Ag + (size_t)row * D + k0 + cseg * 16);
            cpasync16(bs_addr[s] + dsto, Bg + (size_t)row * D + k0 + cseg * 16);
        }
        CP_COMMIT();
    };

    int t0 = blockIdx.x;
    if (t0 >= NTILES) return;

    int bi, bj;
    decode_tile(t0, bi, bj);
    const int8_t* Ag = g_reps + (size_t)bi * BM * D;
    const int8_t* Bg = g_reps + (size_t)bj * BN * D;

    // prologue: first tile's chunk 0
    issue_copy(0, Ag, Bg, 0);

    for (int t = t0; t < NTILES; t += GRID_P) {
        bool offdiag = (bi != bj);
        int bin = 0, bjn = 0;
        const int8_t* Agn = 0;
        const int8_t* Bgn = 0;
        bool have_next = (t + GRID_P < NTILES);
        if (have_next) {
            decode_tile(t + GRID_P, bin, bjn);
            Agn = g_reps + (size_t)bin * BM * D;
            Bgn = g_reps + (size_t)bjn * BN * D;
        }

        int acc[4][8][4];
#pragma unroll
        for (int i = 0; i < 4; i++)
#pragma unroll
            for (int j = 0; j < 8; j++)
#pragma unroll
                for (int k = 0; k < 4; k++) acc[i][j][k] = 0;

#pragma unroll
        for (int kt = 0; kt < NKT; kt++) {
            CP_WAIT0();          // chunk kt retired
            __syncthreads();     // data visible; other stage drained
            if (kt + 1 < NKT) {
                issue_copy((kt + 1) & 1, Ag, Bg, kt + 1);
            } else if (have_next) {
                issue_copy(0, Agn, Bgn, 0);   // next tile chunk0 -> stage 0
            }

            int s = kt & 1;
            uint32_t ab = as_addr[s];
            uint32_t bb = bs_addr[s];

#pragma unroll
            for (int kk = 0; kk < 2; kk++) {
                uint32_t a[4][4], b[4][4];
#pragma unroll
                for (int mi = 0; mi < 4; mi++) {
                    uint32_t addr = ab + (uint32_t)((a_rowoff + mi * 16) * RSB
                                                    + kk * 32 + a_byte);
                    ldsm_x4(a[mi], addr);
                }
#pragma unroll
                for (int nh = 0; nh < 4; nh++) {
                    uint32_t addr = bb + (uint32_t)((b_rowoff + nh * 16) * RSB
                                                    + kk * 32 + b_byte);
                    ldsm_x4(b[nh], addr);
                }
#pragma unroll
                for (int mi = 0; mi < 4; mi++)
#pragma unroll
                    for (int nh = 0; nh < 4; nh++) {
                        mma16832s8(acc[mi][2 * nh],     a[mi], &b[nh][0]);
                        mma16832s8(acc[mi][2 * nh + 1], a[mi], &b[nh][2]);
                    }
            }
        }

        // ---- epilogue: f16x2 exp2 + HADD2 reductions -> global atomics ----
        float* growA = g_rowsum + bi * BM;
        float* growB = g_rowsum + bj * BN;

        __half2 cs_h2[8];
#pragma unroll
        for (int ni = 0; ni < 8; ni++) cs_h2[ni] = __float2half2_rn(0.f);

#pragma unroll
        for (int mi = 0; mi < 4; mi++) {
#pragma unroll
            for (int h = 0; h < 2; h++) {
                __half2 s_h2 = __float2half2_rn(0.f);
#pragma unroll
                for (int ni = 0; ni < 8; ni++) {
                    float f0 = SC2 * (float)acc[mi][ni][2 * h];
                    float f1 = SC2 * (float)acc[mi][ni][2 * h + 1];
                    __half2 he = h2exp2(__floats2half2_rn(f0, f1));
                    s_h2 = __hadd2(s_h2, he);
                    cs_h2[ni] = __hadd2(cs_h2[ni], he);
                }
                float2 sf = __half22float2(s_h2);
                float s = sf.x + sf.y;
                s += __shfl_xor_sync(0xffffffffu, s, 1);
                s += __shfl_xor_sync(0xffffffffu, s, 2);
                if (tc == 0)
                    atomicAdd(&growA[mbase + mi * 16 + h * 8 + g], s);
            }
        }
        if (offdiag) {
#pragma unroll
            for (int ni = 0; ni < 8; ni++) {
                __half2 c = cs_h2[ni];
                c = __hadd2(c, shfl_xor_h2(c, 4));
                c = __hadd2(c, shfl_xor_h2(c, 8));
                c = __hadd2(c, shfl_xor_h2(c, 16));
                if (g == 0) {
                    float2 cf = __half22float2(c);
                    atomicAdd(&growB[nbase + ni * 8 + 2 * tc],     cf.x);
                    atomicAdd(&growB[nbase + ni * 8 + 2 * tc + 1], cf.y);
                }
            }
        }
        // No trailing barrier: next tile's kt=0 wait+sync orders smem reuse.

        bi = bin; bj = bjn; Ag = Agn; Bg = Bgn;
    }
}

// ---------------------------------------------------------------------------
// Kernel 3: finalize (parallel).
// ---------------------------------------------------------------------------
__global__ void finalize_kernel(float* __restrict__ out, int N2) {
    __shared__ float sdata[256];
    int tid  = threadIdx.x;
    int gidx = blockIdx.x * 256 + tid;
    int stride = gridDim.x * 256;

    float local = 0.f;
    for (int i = gidx; i < N2; i += stride) {
        float pos = g_pos[i];
        float rs  = g_rowsum[i] + __expf(pos) - g_diag[i];
        local += logf(rs) - pos;
    }
    sdata[tid] = local;
    __syncthreads();
#pragma unroll
    for (int s = 128; s; s >>= 1) {
        if (tid < s) sdata[tid] += sdata[tid + s];
        __syncthreads();
    }
    if (tid == 0) atomicAdd(out, sdata[0] / (float)N2);
}

// ---------------------------------------------------------------------------
extern "C" void kernel_launch(void* const* d_in, const int* in_sizes, int n_in,
                              void* d_out, int out_size) {
    const float* z1 = (const float*)d_in[0];
    const float* z2 = (const float*)d_in[1];
    int B  = in_sizes[0] / D;   // 4096
    int N2 = 2 * B;             // 8192

    int threads = 256;
    int blocks  = (B * 32 + threads - 1) / threads;
    normalize_kernel<<<blocks, threads>>>(z1, z2, B, (float*)d_out);

    simsum_kernel<<<GRID_P, 128>>>();

    finalize_kernel<<<16, 256>>>((float*)d_out, N2);
}